// round 14
// baseline (speedup 1.0000x reference)
#include <cuda_runtime.h>
#include <cuda_fp16.h>
#include <cuda_bf16.h>
#include <stdint.h>

#define NMAX 50000
#define DIM  64
#define CAP  96     // padded-CSR capacity per node (mean deg ~24; P(>96) ~ e^-61)

// ---------------- scratch (static device globals; no allocation) -------------
__device__ __align__(128) __half g_ht16[(size_t)NMAX * DIM]; // tangent feats (fp16, interleaved)
__device__ __align__(128) float  g_h1[(size_t)NMAX * DIM];   // layer-1 output
__device__ int   g_cnt[NMAX];                 // per-node fill cursor == degree count
__device__ int2  g_cm[(size_t)NMAX * CAP];    // padded CSR: (col, mask-bits)
__device__ int   g_is64;

// ---------------- helpers ----------------------------------------------------
__device__ __forceinline__ float wsum(float v) {
#pragma unroll
    for (int o = 16; o; o >>= 1) v += __shfl_xor_sync(0xffffffffu, v, o);
    return v;
}
__device__ __forceinline__ float artanh_c(float x) {
    x = fminf(fmaxf(x, -1.0f + 1e-5f), 1.0f - 1e-5f);
    return 0.5f * __logf((1.0f + x) / (1.0f - x));
}
__device__ __forceinline__ float tanh_c(float x) {
    return tanhf(fminf(fmaxf(x, -15.0f), 15.0f));
}

// ---------------- transform body (HypLinear + logmap0) -------------------------
// k-loop: 1 broadcast LDS.128 (4 nodes' x_k) + 1 LDS.64 (paired weights)
// + 8 scalar FFMA.
__device__ __forceinline__ void transform_body(const float* __restrict__ x,
                                               const float* __restrict__ W,
                                               const float* __restrict__ b,
                                               int n, int bid)
{
    __shared__ float2 sW2[64 * 32];           // [k*32+j] = (W[j][k], W[j+32][k])
    __shared__ float  sbias[64];
    __shared__ float  sy2;
    __shared__ __align__(16) float4 sxT[8][64];  // [warp][k] = x_k of 4 nodes

    const int tid = threadIdx.x, warp = tid >> 5, lane = tid & 31;

    for (int i = tid; i < 4096; i += 256) {
        int j = i >> 6, k = i & 63;
        if (j < 32) sW2[k * 32 + j].x = W[i];
        else        sW2[k * 32 + (j - 32)].y = W[i];
    }
    if (warp == 0) {
        float b0 = b[lane], b1 = b[lane + 32];
        float bn = fmaxf(sqrtf(wsum(b0 * b0 + b1 * b1)), 1e-7f);
        float t  = tanh_c(bn);
        float p0 = t * b0 / bn, p1 = t * b1 / bn;
        float pn2 = wsum(p0 * p0 + p1 * p1);
        float pn  = fmaxf(sqrtf(pn2), 1e-7f);
        if (pn > 1.0f - 1e-5f) { float s = (1.0f - 1e-5f) / pn; p0 *= s; p1 *= s; pn2 *= s * s; }
        sbias[lane] = p0; sbias[lane + 32] = p1;
        if (lane == 0) sy2 = pn2;
    }
    __syncthreads();

    int base = (bid * 8 + warp) * 4;
    if (base >= n) return;

    float x0[4], x1[4];
#pragma unroll
    for (int r = 0; r < 4; r++) {
        int node = base + r;
        float v0 = 0.f, v1 = 0.f;
        if (node < n) {
            v0 = x[(size_t)node * 64 + lane];
            v1 = x[(size_t)node * 64 + 32 + lane];
        }
        x0[r] = v0; x1[r] = v1;
    }
    sxT[warp][lane]      = make_float4(x0[0], x0[1], x0[2], x0[3]);
    sxT[warp][lane + 32] = make_float4(x1[0], x1[1], x1[2], x1[3]);
    __syncwarp();

    float a0[4] = {0.f, 0.f, 0.f, 0.f};
    float a1[4] = {0.f, 0.f, 0.f, 0.f};
#pragma unroll
    for (int k = 0; k < 64; k++) {
        float4 xk = sxT[warp][k];
        float2 w  = sW2[k * 32 + lane];
        a0[0] = fmaf(xk.x, w.x, a0[0]);
        a0[1] = fmaf(xk.y, w.x, a0[1]);
        a0[2] = fmaf(xk.z, w.x, a0[2]);
        a0[3] = fmaf(xk.w, w.x, a0[3]);
        a1[0] = fmaf(xk.x, w.y, a1[0]);
        a1[1] = fmaf(xk.y, w.y, a1[1]);
        a1[2] = fmaf(xk.z, w.y, a1[2]);
        a1[3] = fmaf(xk.w, w.y, a1[3]);
    }

    float y2 = sy2;
    float p0 = sbias[lane], p1 = sbias[lane + 32];
    __half2* ht2 = (__half2*)g_ht16;

#pragma unroll
    for (int r = 0; r < 4; r++) {
        int node = base + r;
        if (node >= n) break;
        float xn  = fmaxf(sqrtf(wsum(x0[r] * x0[r] + x1[r] * x1[r])), 1e-7f);
        float mxn = fmaxf(sqrtf(wsum(a0[r] * a0[r] + a1[r] * a1[r])), 1e-7f);
        float t   = tanh_c(mxn / xn * artanh_c(xn));
        float h0 = t * a0[r] / mxn, h1 = t * a1[r] / mxn;
        float hn2 = wsum(h0 * h0 + h1 * h1);
        float hn  = fmaxf(sqrtf(hn2), 1e-7f);
        if (hn > 1.0f - 1e-5f) { float s = (1.0f - 1e-5f) / hn; h0 *= s; h1 *= s; hn2 *= s * s; }
        float xy  = wsum(h0 * p0 + h1 * p1);
        float cA  = 1.0f + 2.0f * xy + y2;
        float cB  = 1.0f - hn2;
        float den = fmaxf(1.0f + 2.0f * xy + hn2 * y2, 1e-7f);
        float q0 = (cA * h0 + cB * p0) / den;
        float q1 = (cA * h1 + cB * p1) / den;
        float qn = fmaxf(sqrtf(wsum(q0 * q0 + q1 * q1)), 1e-7f);
        if (qn > 1.0f - 1e-5f) { float s = (1.0f - 1e-5f) / qn; q0 *= s; q1 *= s; qn = 1.0f - 1e-5f; }
        float l = artanh_c(qn) / qn;
        ht2[(size_t)node * 32 + lane] = __floats2half2_rn(l * q0, l * q1);
    }
}

// ---------------- K1: transform layer-1  ∥  zero counters + dtype detect -----
__global__ void prep_kernel(const float* __restrict__ x,
                            const float* __restrict__ W,
                            const float* __restrict__ b,
                            int n, int tgrid,
                            const long long* __restrict__ e64, int E, int N)
{
    if ((int)blockIdx.x < tgrid) {
        transform_body(x, W, b, n, blockIdx.x);
        return;
    }
    int i = ((int)blockIdx.x - tgrid) * 256 + threadIdx.x;
    if (i < n) g_cnt[i] = 0;
    if (i == 0) {
        int ok = 1;
        int cnt = E < 64 ? E : 64;
        for (int k = 0; k < cnt; k++) {
            long long v = e64[k];
            if (v < 0 || v >= (long long)N) { ok = 0; break; }
        }
        g_is64 = ok;
    }
}

// plain transform launch (layer 2)
__global__ void transform_kernel(const float* __restrict__ x,
                                 const float* __restrict__ W,
                                 const float* __restrict__ b,
                                 int n)
{
    transform_body(x, W, b, n, blockIdx.x);
}

// ---------------- K2: single-pass padded-CSR fill ------------------------------
__global__ void fill_kernel(const void* __restrict__ edges_raw,
                            const float* __restrict__ em, int E)
{
    int eid = blockIdx.x * blockDim.x + threadIdx.x;
    if (eid >= E) return;
    int r, c;
    if (g_is64) {
        const long long* e = (const long long*)edges_raw;
        r = (int)__ldg(&e[eid]);
        c = (int)__ldg(&e[(size_t)E + eid]);
    } else {
        const int* e = (const int*)edges_raw;
        r = __ldg(&e[eid]);
        c = __ldg(&e[(size_t)E + eid]);
    }
    float m = __ldg(&em[eid]);
    int rank = atomicAdd(&g_cnt[r], 1);
    if (rank < CAP)
        g_cm[(size_t)r * CAP + rank] = make_int2(c, __float_as_int(m));
}

// ---------------- gather + HypAgg + HypAct --------------------------------------
__global__ void __launch_bounds__(256)
gather_finalize_kernel(const float* __restrict__ node_mask,
                       float* __restrict__ out, int n)
{
    int warp = threadIdx.x >> 5, lane = threadIdx.x & 31;
    int node = blockIdx.x * 8 + warp;
    if (node >= n) return;

    int cntv = g_cnt[node]; if (cntv > CAP) cntv = CAP;
    int beg = node * CAP, end = beg + cntv;
    int quarter = lane >> 3, sub = lane & 7;

    const uint4* ht4 = (const uint4*)g_ht16;   // row = 8 x uint4
    float2 facc[4];
#pragma unroll
    for (int w = 0; w < 4; w++) facc[w] = make_float2(0.f, 0.f);
    float dm = 0.f;

    for (int base = beg; base < end; base += 16) {
        int lim = end; if (lim > base + 16) lim = base + 16;
        __half2 hz = __float2half2_rn(0.f);
        __half2 hacc0 = hz, hacc1 = hz, hacc2 = hz, hacc3 = hz;
#pragma unroll 4
        for (int j = base + quarter; j < lim; j += 4) {
            int2 cm = __ldg(&g_cm[j]);
            float m = __int_as_float(cm.y);
            __half2 mh = __float2half2_rn(m);
            uint4 v = __ldg(&ht4[(size_t)cm.x * 8 + sub]);
            hacc0 = __hfma2(*(const __half2*)&v.x, mh, hacc0);
            hacc1 = __hfma2(*(const __half2*)&v.y, mh, hacc1);
            hacc2 = __hfma2(*(const __half2*)&v.z, mh, hacc2);
            hacc3 = __hfma2(*(const __half2*)&v.w, mh, hacc3);
            if (sub == 0) dm += m;
        }
        float2 f0 = __half22float2(hacc0);
        float2 f1 = __half22float2(hacc1);
        float2 f2 = __half22float2(hacc2);
        float2 f3 = __half22float2(hacc3);
        facc[0].x += f0.x; facc[0].y += f0.y;
        facc[1].x += f1.x; facc[1].y += f1.y;
        facc[2].x += f2.x; facc[2].y += f2.y;
        facc[3].x += f3.x; facc[3].y += f3.y;
    }

    float d = fmaxf(wsum(dm), 1.0f);

#pragma unroll
    for (int w = 0; w < 4; w++) {
        facc[w].x += __shfl_xor_sync(0xffffffffu, facc[w].x, 8);
        facc[w].y += __shfl_xor_sync(0xffffffffu, facc[w].y, 8);
        facc[w].x += __shfl_xor_sync(0xffffffffu, facc[w].x, 16);
        facc[w].y += __shfl_xor_sync(0xffffffffu, facc[w].y, 16);
    }

    float inv_d = 1.0f / d;
    float a[8];
#pragma unroll
    for (int w = 0; w < 4; w++) { a[2*w] = facc[w].x * inv_d; a[2*w+1] = facc[w].y * inv_d; }

    float n2 = 0.f;
#pragma unroll
    for (int k = 0; k < 8; k++) n2 += a[k] * a[k];
    float an = fmaxf(sqrtf(wsum(n2) * 0.25f), 1e-7f);
    float t  = tanh_c(an);
    float s1 = t / an;
    float hh[8];
#pragma unroll
    for (int k = 0; k < 8; k++) hh[k] = s1 * a[k];
    float hn = fmaxf(t, 1e-7f);
    if (hn > 1.0f - 1e-5f) {
        float s = (1.0f - 1e-5f) / hn;
#pragma unroll
        for (int k = 0; k < 8; k++) hh[k] *= s;
        hn = 1.0f - 1e-5f;
    }

    float l = artanh_c(hn) / hn;
    float u[8];
    float un2 = 0.f;
#pragma unroll
    for (int k = 0; k < 8; k++) { u[k] = fmaxf(l * hh[k], 0.f); un2 += u[k] * u[k]; }

    float un = fmaxf(sqrtf(wsum(un2) * 0.25f), 1e-7f);
    float t2 = tanh_c(un);
    float s2 = t2 / un;
    float o[8];
#pragma unroll
    for (int k = 0; k < 8; k++) o[k] = s2 * u[k];
    if (t2 > 1.0f - 1e-5f) {
        float s = (1.0f - 1e-5f) / t2;
#pragma unroll
        for (int k = 0; k < 8; k++) o[k] *= s;
    }

    if (quarter == 0) {
        float nm = node_mask[node];
        float4 lo = make_float4(o[0] * nm, o[2] * nm, o[4] * nm, o[6] * nm);
        float4 hi = make_float4(o[1] * nm, o[3] * nm, o[5] * nm, o[7] * nm);
        *(float4*)(out + (size_t)node * 64 + 4 * sub)      = lo;
        *(float4*)(out + (size_t)node * 64 + 32 + 4 * sub) = hi;
    }
}

// ---------------- launch -----------------------------------------------------
extern "C" void kernel_launch(void* const* d_in, const int* in_sizes, int n_in,
                              void* d_out, int out_size)
{
    const float* h         = (const float*)d_in[0];
    const void*  edges     = d_in[2];
    const float* node_mask = (const float*)d_in[3];
    const float* edge_mask = (const float*)d_in[4];
    const float* W0        = (const float*)d_in[5];
    const float* b0        = (const float*)d_in[6];
    const float* W1        = (const float*)d_in[7];
    const float* b1        = (const float*)d_in[8];
    float*       out       = (float*)d_out;

    int N = in_sizes[0] / 64;
    int E = in_sizes[4];

    void* h1p = nullptr;
    cudaGetSymbolAddress(&h1p, g_h1);
    float* h1 = (float*)h1p;

    int tgrid = (N + 31) / 32;
    int ggrid = (N + 7) / 8;
    int egrid = (E + 255) / 256;
    int ngrid = (N + 255) / 256;

    // K1: transform layer-1 ∥ zero+detect
    prep_kernel<<<tgrid + ngrid, 256>>>(h, W0, b0, N, tgrid,
                                        (const long long*)edges, E, N);
    // K2: single-pass padded-CSR fill
    fill_kernel<<<egrid, 256>>>(edges, edge_mask, E);
    // K3: layer-1 aggregate+activate
    gather_finalize_kernel<<<ggrid, 256>>>(node_mask, h1, N);
    // K4..K5: layer 2
    transform_kernel<<<tgrid, 256>>>(h1, W1, b1, N);
    gather_finalize_kernel<<<ggrid, 256>>>(node_mask, out, N);
}

// round 15
// speedup vs baseline: 1.2514x; 1.2514x over previous
#include <cuda_runtime.h>
#include <cuda_fp16.h>
#include <cuda_bf16.h>
#include <stdint.h>

#define NMAX 50000
#define DIM  64
#define CAP  96     // padded-CSR capacity per node (mean deg ~24; P(>96) ~ e^-61)

// ---------------- scratch (static device globals; no allocation) -------------
__device__ __align__(128) __half g_ht16[(size_t)NMAX * DIM]; // tangent feats (fp16, interleaved)
__device__ __align__(128) float  g_h1[(size_t)NMAX * DIM];   // layer-1 output
__device__ int   g_cnt[NMAX];                 // per-node fill cursor == degree count
__device__ int2  g_cm[(size_t)NMAX * CAP];    // padded CSR: (col, mask-bits)
__device__ int   g_is64;

// ---------------- helpers ----------------------------------------------------
__device__ __forceinline__ float wsum(float v) {
#pragma unroll
    for (int o = 16; o; o >>= 1) v += __shfl_xor_sync(0xffffffffu, v, o);
    return v;
}
// fast artanh: MUFU lg2 based
__device__ __forceinline__ float artanh_c(float x) {
    x = fminf(fmaxf(x, -1.0f + 1e-5f), 1.0f - 1e-5f);
    return 0.5f * __logf(__fdividef(1.0f + x, 1.0f - x));
}
// fast tanh: MUFU ex2 based
__device__ __forceinline__ float tanh_c(float x) {
    x = fminf(fmaxf(x, -15.0f), 15.0f);
    float e = __expf(2.0f * x);
    return __fdividef(e - 1.0f, e + 1.0f);
}

// ---------------- transform body (HypLinear + logmap0), R13 k-loop ------------
__device__ __forceinline__ void transform_body(const float* __restrict__ x,
                                               const float* __restrict__ W,
                                               const float* __restrict__ b,
                                               int n, int bid)
{
    __shared__ float sW[64 * 65];
    __shared__ float sbias[64];
    __shared__ float sy2;
    __shared__ float sx[8][4][64];

    const int tid = threadIdx.x, warp = tid >> 5, lane = tid & 31;

    for (int i = tid; i < 4096; i += 256) {
        int j = i >> 6, k = i & 63;
        sW[k * 65 + j] = W[i];
    }
    if (warp == 0) {
        float b0 = b[lane], b1 = b[lane + 32];
        float bn = fmaxf(sqrtf(wsum(b0 * b0 + b1 * b1)), 1e-7f);
        float t  = tanh_c(bn);
        float inv = __fdividef(t, bn);
        float p0 = inv * b0, p1 = inv * b1;
        float pn2 = wsum(p0 * p0 + p1 * p1);
        float pn  = fmaxf(sqrtf(pn2), 1e-7f);
        if (pn > 1.0f - 1e-5f) { float s = (1.0f - 1e-5f) / pn; p0 *= s; p1 *= s; pn2 *= s * s; }
        sbias[lane] = p0; sbias[lane + 32] = p1;
        if (lane == 0) sy2 = pn2;
    }
    __syncthreads();

    int base = (bid * 8 + warp) * 4;
    if (base >= n) return;

    float x0[4], x1[4], a0[4], a1[4];
#pragma unroll
    for (int r = 0; r < 4; r++) {
        int node = base + r;
        float v0 = 0.f, v1 = 0.f;
        if (node < n) {
            v0 = x[(size_t)node * 64 + lane];
            v1 = x[(size_t)node * 64 + 32 + lane];
        }
        x0[r] = v0; x1[r] = v1; a0[r] = 0.f; a1[r] = 0.f;
        sx[warp][r][lane] = v0; sx[warp][r][lane + 32] = v1;
    }
    __syncwarp();

#pragma unroll
    for (int k = 0; k < 64; k++) {
        float w0 = sW[k * 65 + lane];
        float w1 = sW[k * 65 + lane + 32];
#pragma unroll
        for (int r = 0; r < 4; r++) {
            float xk = sx[warp][r][k];
            a0[r] = fmaf(xk, w0, a0[r]);
            a1[r] = fmaf(xk, w1, a1[r]);
        }
    }

    float y2 = sy2;
    float p0 = sbias[lane], p1 = sbias[lane + 32];
    __half2* ht2 = (__half2*)g_ht16;

#pragma unroll
    for (int r = 0; r < 4; r++) {
        int node = base + r;
        if (node >= n) break;
        float xn  = fmaxf(sqrtf(wsum(x0[r] * x0[r] + x1[r] * x1[r])), 1e-7f);
        float mxn = fmaxf(sqrtf(wsum(a0[r] * a0[r] + a1[r] * a1[r])), 1e-7f);
        float t   = tanh_c(__fdividef(mxn, xn) * artanh_c(xn));
        float inv1 = __fdividef(t, mxn);
        float h0 = inv1 * a0[r], h1 = inv1 * a1[r];
        float hn2 = wsum(h0 * h0 + h1 * h1);
        float hn  = fmaxf(sqrtf(hn2), 1e-7f);
        if (hn > 1.0f - 1e-5f) { float s = __fdividef(1.0f - 1e-5f, hn); h0 *= s; h1 *= s; hn2 *= s * s; }
        float xy  = wsum(h0 * p0 + h1 * p1);
        float cA  = 1.0f + 2.0f * xy + y2;
        float cB  = 1.0f - hn2;
        float den = fmaxf(1.0f + 2.0f * xy + hn2 * y2, 1e-7f);
        float invden = __fdividef(1.0f, den);
        float q0 = (cA * h0 + cB * p0) * invden;
        float q1 = (cA * h1 + cB * p1) * invden;
        float qn = fmaxf(sqrtf(wsum(q0 * q0 + q1 * q1)), 1e-7f);
        if (qn > 1.0f - 1e-5f) { float s = __fdividef(1.0f - 1e-5f, qn); q0 *= s; q1 *= s; qn = 1.0f - 1e-5f; }
        float l = __fdividef(artanh_c(qn), qn);
        ht2[(size_t)node * 32 + lane] = __floats2half2_rn(l * q0, l * q1);
    }
}

// ---------------- K1: transform layer-1  ∥  zero counters + dtype detect -----
__global__ void prep_kernel(const float* __restrict__ x,
                            const float* __restrict__ W,
                            const float* __restrict__ b,
                            int n, int tgrid,
                            const long long* __restrict__ e64, int E, int N)
{
    if ((int)blockIdx.x < tgrid) {
        transform_body(x, W, b, n, blockIdx.x);
        return;
    }
    int i = ((int)blockIdx.x - tgrid) * 256 + threadIdx.x;
    if (i < n) g_cnt[i] = 0;
    if (i == 0) {
        int ok = 1;
        int cnt = E < 64 ? E : 64;
        for (int k = 0; k < cnt; k++) {
            long long v = e64[k];
            if (v < 0 || v >= (long long)N) { ok = 0; break; }
        }
        g_is64 = ok;
    }
}

// plain transform launch (layer 2)
__global__ void transform_kernel(const float* __restrict__ x,
                                 const float* __restrict__ W,
                                 const float* __restrict__ b,
                                 int n)
{
    transform_body(x, W, b, n, blockIdx.x);
}

// ---------------- K2: single-pass padded-CSR fill ------------------------------
__global__ void fill_kernel(const void* __restrict__ edges_raw,
                            const float* __restrict__ em, int E)
{
    int eid = blockIdx.x * blockDim.x + threadIdx.x;
    if (eid >= E) return;
    int r, c;
    if (g_is64) {
        const long long* e = (const long long*)edges_raw;
        r = (int)__ldg(&e[eid]);
        c = (int)__ldg(&e[(size_t)E + eid]);
    } else {
        const int* e = (const int*)edges_raw;
        r = __ldg(&e[eid]);
        c = __ldg(&e[(size_t)E + eid]);
    }
    float m = __ldg(&em[eid]);
    int rank = atomicAdd(&g_cnt[r], 1);
    if (rank < CAP)
        g_cm[(size_t)r * CAP + rank] = make_int2(c, __float_as_int(m));
}

// ---------------- gather + HypAgg + HypAct --------------------------------------
__global__ void __launch_bounds__(256)
gather_finalize_kernel(const float* __restrict__ node_mask,
                       float* __restrict__ out, int n)
{
    int warp = threadIdx.x >> 5, lane = threadIdx.x & 31;
    int node = blockIdx.x * 8 + warp;
    if (node >= n) return;

    int cntv = g_cnt[node]; if (cntv > CAP) cntv = CAP;
    int beg = node * CAP, end = beg + cntv;
    int quarter = lane >> 3, sub = lane & 7;

    const uint4* ht4 = (const uint4*)g_ht16;   // row = 8 x uint4
    float2 facc[4];
#pragma unroll
    for (int w = 0; w < 4; w++) facc[w] = make_float2(0.f, 0.f);
    float dm = 0.f;

    for (int base = beg; base < end; base += 16) {
        int lim = end; if (lim > base + 16) lim = base + 16;
        __half2 hz = __float2half2_rn(0.f);
        __half2 hacc0 = hz, hacc1 = hz, hacc2 = hz, hacc3 = hz;
#pragma unroll 4
        for (int j = base + quarter; j < lim; j += 4) {
            int2 cm = __ldg(&g_cm[j]);
            float m = __int_as_float(cm.y);
            __half2 mh = __float2half2_rn(m);
            uint4 v = __ldg(&ht4[(size_t)cm.x * 8 + sub]);
            hacc0 = __hfma2(*(const __half2*)&v.x, mh, hacc0);
            hacc1 = __hfma2(*(const __half2*)&v.y, mh, hacc1);
            hacc2 = __hfma2(*(const __half2*)&v.z, mh, hacc2);
            hacc3 = __hfma2(*(const __half2*)&v.w, mh, hacc3);
            if (sub == 0) dm += m;
        }
        float2 f0 = __half22float2(hacc0);
        float2 f1 = __half22float2(hacc1);
        float2 f2 = __half22float2(hacc2);
        float2 f3 = __half22float2(hacc3);
        facc[0].x += f0.x; facc[0].y += f0.y;
        facc[1].x += f1.x; facc[1].y += f1.y;
        facc[2].x += f2.x; facc[2].y += f2.y;
        facc[3].x += f3.x; facc[3].y += f3.y;
    }

    float d = fmaxf(wsum(dm), 1.0f);

#pragma unroll
    for (int w = 0; w < 4; w++) {
        facc[w].x += __shfl_xor_sync(0xffffffffu, facc[w].x, 8);
        facc[w].y += __shfl_xor_sync(0xffffffffu, facc[w].y, 8);
        facc[w].x += __shfl_xor_sync(0xffffffffu, facc[w].x, 16);
        facc[w].y += __shfl_xor_sync(0xffffffffu, facc[w].y, 16);
    }

    float inv_d = __fdividef(1.0f, d);
    float a[8];
#pragma unroll
    for (int w = 0; w < 4; w++) { a[2*w] = facc[w].x * inv_d; a[2*w+1] = facc[w].y * inv_d; }

    float n2 = 0.f;
#pragma unroll
    for (int k = 0; k < 8; k++) n2 += a[k] * a[k];
    float an = fmaxf(sqrtf(wsum(n2) * 0.25f), 1e-7f);
    float t  = tanh_c(an);
    float s1 = __fdividef(t, an);
    float hh[8];
#pragma unroll
    for (int k = 0; k < 8; k++) hh[k] = s1 * a[k];
    float hn = fmaxf(t, 1e-7f);
    if (hn > 1.0f - 1e-5f) {
        float s = __fdividef(1.0f - 1e-5f, hn);
#pragma unroll
        for (int k = 0; k < 8; k++) hh[k] *= s;
        hn = 1.0f - 1e-5f;
    }

    float l = __fdividef(artanh_c(hn), hn);
    float u[8];
    float un2 = 0.f;
#pragma unroll
    for (int k = 0; k < 8; k++) { u[k] = fmaxf(l * hh[k], 0.f); un2 += u[k] * u[k]; }

    float un = fmaxf(sqrtf(wsum(un2) * 0.25f), 1e-7f);
    float t2 = tanh_c(un);
    float s2 = __fdividef(t2, un);
    float o[8];
#pragma unroll
    for (int k = 0; k < 8; k++) o[k] = s2 * u[k];
    if (t2 > 1.0f - 1e-5f) {
        float s = __fdividef(1.0f - 1e-5f, t2);
#pragma unroll
        for (int k = 0; k < 8; k++) o[k] *= s;
    }

    if (quarter == 0) {
        float nm = node_mask[node];
        float4 lo = make_float4(o[0] * nm, o[2] * nm, o[4] * nm, o[6] * nm);
        float4 hi = make_float4(o[1] * nm, o[3] * nm, o[5] * nm, o[7] * nm);
        *(float4*)(out + (size_t)node * 64 + 4 * sub)      = lo;
        *(float4*)(out + (size_t)node * 64 + 32 + 4 * sub) = hi;
    }
}

// ---------------- launch -----------------------------------------------------
extern "C" void kernel_launch(void* const* d_in, const int* in_sizes, int n_in,
                              void* d_out, int out_size)
{
    const float* h         = (const float*)d_in[0];
    const void*  edges     = d_in[2];
    const float* node_mask = (const float*)d_in[3];
    const float* edge_mask = (const float*)d_in[4];
    const float* W0        = (const float*)d_in[5];
    const float* b0        = (const float*)d_in[6];
    const float* W1        = (const float*)d_in[7];
    const float* b1        = (const float*)d_in[8];
    float*       out       = (float*)d_out;

    int N = in_sizes[0] / 64;
    int E = in_sizes[4];

    void* h1p = nullptr;
    cudaGetSymbolAddress(&h1p, g_h1);
    float* h1 = (float*)h1p;

    int tgrid = (N + 31) / 32;
    int ggrid = (N + 7) / 8;
    int egrid = (E + 255) / 256;
    int ngrid = (N + 255) / 256;

    // K1: transform layer-1 ∥ zero+detect
    prep_kernel<<<tgrid + ngrid, 256>>>(h, W0, b0, N, tgrid,
                                        (const long long*)edges, E, N);
    // K2: single-pass padded-CSR fill
    fill_kernel<<<egrid, 256>>>(edges, edge_mask, E);
    // K3: layer-1 aggregate+activate
    gather_finalize_kernel<<<ggrid, 256>>>(node_mask, h1, N);
    // K4..K5: layer 2
    transform_kernel<<<tgrid, 256>>>(h1, W1, b1, N);
    gather_finalize_kernel<<<ggrid, 256>>>(node_mask, out, N);
}

// round 16
// speedup vs baseline: 1.3513x; 1.0799x over previous
#include <cuda_runtime.h>
#include <cuda_fp16.h>
#include <cuda_bf16.h>
#include <stdint.h>

#define NMAX 50000
#define DIM  64
#define CAP  96     // padded-CSR capacity per node (mean deg ~24; P(>96) ~ e^-61)

// ---------------- scratch (static device globals; no allocation) -------------
__device__ __align__(128) __half g_ht16[(size_t)NMAX * DIM]; // tangent feats (fp16, interleaved)
__device__ __align__(128) float  g_h1[(size_t)NMAX * DIM];   // layer-1 output
__device__ int   g_cnt[NMAX];                 // per-node fill cursor == degree count
__device__ int2  g_cm[(size_t)NMAX * CAP];    // padded CSR: (col, mask-bits)
__device__ int   g_is64;

// ---------------- helpers ----------------------------------------------------
__device__ __forceinline__ float wsum(float v) {
#pragma unroll
    for (int o = 16; o; o >>= 1) v += __shfl_xor_sync(0xffffffffu, v, o);
    return v;
}
// fast artanh: MUFU lg2 based
__device__ __forceinline__ float artanh_c(float x) {
    x = fminf(fmaxf(x, -1.0f + 1e-5f), 1.0f - 1e-5f);
    return 0.5f * __logf(__fdividef(1.0f + x, 1.0f - x));
}
// fast tanh: MUFU ex2 based
__device__ __forceinline__ float tanh_c(float x) {
    x = fminf(fmaxf(x, -15.0f), 15.0f);
    float e = __expf(2.0f * x);
    return __fdividef(e - 1.0f, e + 1.0f);
}

// ---------------- transform body (HypLinear + logmap0) -------------------------
// k-loop: 2 broadcast LDS.64 (x pairs) + 2 LDS.32 (weights) + 8 scalar FMA.
// Epilogue uses the identity |h| = |t * a / |a|| = t (one fewer warp reduction).
__device__ __forceinline__ void transform_body(const float* __restrict__ x,
                                               const float* __restrict__ W,
                                               const float* __restrict__ b,
                                               int n, int bid)
{
    __shared__ float  sW[64 * 65];
    __shared__ float  sbias[64];
    __shared__ float  sy2;
    __shared__ __align__(8) float2 sx2[8][2][64];   // [warp][pair][k]

    const int tid = threadIdx.x, warp = tid >> 5, lane = tid & 31;

    for (int i = tid; i < 4096; i += 256) {
        int j = i >> 6, k = i & 63;
        sW[k * 65 + j] = W[i];
    }
    if (warp == 0) {
        float b0 = b[lane], b1 = b[lane + 32];
        float bn = fmaxf(sqrtf(wsum(b0 * b0 + b1 * b1)), 1e-7f);
        float t  = tanh_c(bn);
        float inv = __fdividef(t, bn);
        float p0 = inv * b0, p1 = inv * b1;
        float pn2 = wsum(p0 * p0 + p1 * p1);
        float pn  = fmaxf(sqrtf(pn2), 1e-7f);
        if (pn > 1.0f - 1e-5f) { float s = (1.0f - 1e-5f) / pn; p0 *= s; p1 *= s; pn2 *= s * s; }
        sbias[lane] = p0; sbias[lane + 32] = p1;
        if (lane == 0) sy2 = pn2;
    }
    __syncthreads();

    int base = (bid * 8 + warp) * 4;
    if (base >= n) return;

    float x0[4], x1[4], a0[4], a1[4];
#pragma unroll
    for (int r = 0; r < 4; r++) {
        int node = base + r;
        float v0 = 0.f, v1 = 0.f;
        if (node < n) {
            v0 = x[(size_t)node * 64 + lane];
            v1 = x[(size_t)node * 64 + 32 + lane];
        }
        x0[r] = v0; x1[r] = v1; a0[r] = 0.f; a1[r] = 0.f;
    }
    sx2[warp][0][lane]      = make_float2(x0[0], x0[1]);
    sx2[warp][1][lane]      = make_float2(x0[2], x0[3]);
    // dims 32..63 are stored at k = lane+32
    sx2[warp][0][lane + 32] = make_float2(x1[0], x1[1]);
    sx2[warp][1][lane + 32] = make_float2(x1[2], x1[3]);
    __syncwarp();

#pragma unroll
    for (int k = 0; k < 64; k++) {
        float2 xa = sx2[warp][0][k];   // nodes 0,1
        float2 xb = sx2[warp][1][k];   // nodes 2,3
        float w0 = sW[k * 65 + lane];
        float w1 = sW[k * 65 + lane + 32];
        a0[0] = fmaf(xa.x, w0, a0[0]);
        a0[1] = fmaf(xa.y, w0, a0[1]);
        a0[2] = fmaf(xb.x, w0, a0[2]);
        a0[3] = fmaf(xb.y, w0, a0[3]);
        a1[0] = fmaf(xa.x, w1, a1[0]);
        a1[1] = fmaf(xa.y, w1, a1[1]);
        a1[2] = fmaf(xb.x, w1, a1[2]);
        a1[3] = fmaf(xb.y, w1, a1[3]);
    }

    float y2 = sy2;
    float p0 = sbias[lane], p1 = sbias[lane + 32];
    __half2* ht2 = (__half2*)g_ht16;

#pragma unroll
    for (int r = 0; r < 4; r++) {
        int node = base + r;
        if (node >= n) break;
        float xn  = fmaxf(sqrtf(wsum(x0[r] * x0[r] + x1[r] * x1[r])), 1e-7f);
        float mxn = fmaxf(sqrtf(wsum(a0[r] * a0[r] + a1[r] * a1[r])), 1e-7f);
        float t   = tanh_c(__fdividef(mxn, xn) * artanh_c(xn));
        // h = t*a/mxn  =>  |h| = t (t >= 0 here); proj clips to 1-1e-5
        float hn = fminf(t, 1.0f - 1e-5f);
        float inv1 = __fdividef(hn, mxn);          // folds proj scale into h
        float h0 = inv1 * a0[r], h1 = inv1 * a1[r];
        float hn2 = hn * hn;
        float xy  = wsum(h0 * p0 + h1 * p1);
        float cA  = 1.0f + 2.0f * xy + y2;
        float cB  = 1.0f - hn2;
        float den = fmaxf(1.0f + 2.0f * xy + hn2 * y2, 1e-7f);
        float invden = __fdividef(1.0f, den);
        float q0 = (cA * h0 + cB * p0) * invden;
        float q1 = (cA * h1 + cB * p1) * invden;
        float qn = fmaxf(sqrtf(wsum(q0 * q0 + q1 * q1)), 1e-7f);
        if (qn > 1.0f - 1e-5f) { float s = __fdividef(1.0f - 1e-5f, qn); q0 *= s; q1 *= s; qn = 1.0f - 1e-5f; }
        float l = __fdividef(artanh_c(qn), qn);
        ht2[(size_t)node * 32 + lane] = __floats2half2_rn(l * q0, l * q1);
    }
}

// ---------------- K1: transform layer-1  ∥  zero counters + dtype detect -----
__global__ void prep_kernel(const float* __restrict__ x,
                            const float* __restrict__ W,
                            const float* __restrict__ b,
                            int n, int tgrid,
                            const long long* __restrict__ e64, int E, int N)
{
    if ((int)blockIdx.x < tgrid) {
        transform_body(x, W, b, n, blockIdx.x);
        return;
    }
    int i = ((int)blockIdx.x - tgrid) * 256 + threadIdx.x;
    if (i < n) g_cnt[i] = 0;
    if (i == 0) {
        int ok = 1;
        int cnt = E < 64 ? E : 64;
        for (int k = 0; k < cnt; k++) {
            long long v = e64[k];
            if (v < 0 || v >= (long long)N) { ok = 0; break; }
        }
        g_is64 = ok;
    }
}

// plain transform launch (layer 2)
__global__ void transform_kernel(const float* __restrict__ x,
                                 const float* __restrict__ W,
                                 const float* __restrict__ b,
                                 int n)
{
    transform_body(x, W, b, n, blockIdx.x);
}

// ---------------- K2: single-pass padded-CSR fill ------------------------------
__global__ void fill_kernel(const void* __restrict__ edges_raw,
                            const float* __restrict__ em, int E)
{
    int eid = blockIdx.x * blockDim.x + threadIdx.x;
    if (eid >= E) return;
    int r, c;
    if (g_is64) {
        const long long* e = (const long long*)edges_raw;
        r = (int)__ldg(&e[eid]);
        c = (int)__ldg(&e[(size_t)E + eid]);
    } else {
        const int* e = (const int*)edges_raw;
        r = __ldg(&e[eid]);
        c = __ldg(&e[(size_t)E + eid]);
    }
    float m = __ldg(&em[eid]);
    int rank = atomicAdd(&g_cnt[r], 1);
    if (rank < CAP)
        g_cm[(size_t)r * CAP + rank] = make_int2(c, __float_as_int(m));
}

// ---------------- gather + HypAgg + HypAct --------------------------------------
__global__ void __launch_bounds__(256)
gather_finalize_kernel(const float* __restrict__ node_mask,
                       float* __restrict__ out, int n)
{
    int warp = threadIdx.x >> 5, lane = threadIdx.x & 31;
    int node = blockIdx.x * 8 + warp;
    if (node >= n) return;

    int cntv = g_cnt[node]; if (cntv > CAP) cntv = CAP;
    int beg = node * CAP, end = beg + cntv;
    int quarter = lane >> 3, sub = lane & 7;

    const uint4* ht4 = (const uint4*)g_ht16;   // row = 8 x uint4
    float2 facc[4];
#pragma unroll
    for (int w = 0; w < 4; w++) facc[w] = make_float2(0.f, 0.f);
    float dm = 0.f;

    for (int base = beg; base < end; base += 16) {
        int lim = end; if (lim > base + 16) lim = base + 16;
        __half2 hz = __float2half2_rn(0.f);
        __half2 hacc0 = hz, hacc1 = hz, hacc2 = hz, hacc3 = hz;
#pragma unroll 4
        for (int j = base + quarter; j < lim; j += 4) {
            int2 cm = __ldg(&g_cm[j]);
            float m = __int_as_float(cm.y);
            __half2 mh = __float2half2_rn(m);
            uint4 v = __ldg(&ht4[(size_t)cm.x * 8 + sub]);
            hacc0 = __hfma2(*(const __half2*)&v.x, mh, hacc0);
            hacc1 = __hfma2(*(const __half2*)&v.y, mh, hacc1);
            hacc2 = __hfma2(*(const __half2*)&v.z, mh, hacc2);
            hacc3 = __hfma2(*(const __half2*)&v.w, mh, hacc3);
            if (sub == 0) dm += m;
        }
        float2 f0 = __half22float2(hacc0);
        float2 f1 = __half22float2(hacc1);
        float2 f2 = __half22float2(hacc2);
        float2 f3 = __half22float2(hacc3);
        facc[0].x += f0.x; facc[0].y += f0.y;
        facc[1].x += f1.x; facc[1].y += f1.y;
        facc[2].x += f2.x; facc[2].y += f2.y;
        facc[3].x += f3.x; facc[3].y += f3.y;
    }

    float d = fmaxf(wsum(dm), 1.0f);

#pragma unroll
    for (int w = 0; w < 4; w++) {
        facc[w].x += __shfl_xor_sync(0xffffffffu, facc[w].x, 8);
        facc[w].y += __shfl_xor_sync(0xffffffffu, facc[w].y, 8);
        facc[w].x += __shfl_xor_sync(0xffffffffu, facc[w].x, 16);
        facc[w].y += __shfl_xor_sync(0xffffffffu, facc[w].y, 16);
    }

    float inv_d = __fdividef(1.0f, d);
    float a[8];
#pragma unroll
    for (int w = 0; w < 4; w++) { a[2*w] = facc[w].x * inv_d; a[2*w+1] = facc[w].y * inv_d; }

    float n2 = 0.f;
#pragma unroll
    for (int k = 0; k < 8; k++) n2 += a[k] * a[k];
    float an = fmaxf(sqrtf(wsum(n2) * 0.25f), 1e-7f);
    float t  = tanh_c(an);
    float hn = fminf(t, 1.0f - 1e-5f);
    float s1 = __fdividef(hn, an);
    float hh[8];
#pragma unroll
    for (int k = 0; k < 8; k++) hh[k] = s1 * a[k];

    float l = __fdividef(artanh_c(hn), hn);
    float u[8];
    float un2 = 0.f;
#pragma unroll
    for (int k = 0; k < 8; k++) { u[k] = fmaxf(l * hh[k], 0.f); un2 += u[k] * u[k]; }

    float un = fmaxf(sqrtf(wsum(un2) * 0.25f), 1e-7f);
    float t2 = tanh_c(un);
    float on = fminf(t2, 1.0f - 1e-5f);
    float s2 = __fdividef(on, un);
    float o[8];
#pragma unroll
    for (int k = 0; k < 8; k++) o[k] = s2 * u[k];

    if (quarter == 0) {
        float nm = node_mask[node];
        float4 lo = make_float4(o[0] * nm, o[2] * nm, o[4] * nm, o[6] * nm);
        float4 hi = make_float4(o[1] * nm, o[3] * nm, o[5] * nm, o[7] * nm);
        *(float4*)(out + (size_t)node * 64 + 4 * sub)      = lo;
        *(float4*)(out + (size_t)node * 64 + 32 + 4 * sub) = hi;
    }
}

// ---------------- launch -----------------------------------------------------
extern "C" void kernel_launch(void* const* d_in, const int* in_sizes, int n_in,
                              void* d_out, int out_size)
{
    const float* h         = (const float*)d_in[0];
    const void*  edges     = d_in[2];
    const float* node_mask = (const float*)d_in[3];
    const float* edge_mask = (const float*)d_in[4];
    const float* W0        = (const float*)d_in[5];
    const float* b0        = (const float*)d_in[6];
    const float* W1        = (const float*)d_in[7];
    const float* b1        = (const float*)d_in[8];
    float*       out       = (float*)d_out;

    int N = in_sizes[0] / 64;
    int E = in_sizes[4];

    void* h1p = nullptr;
    cudaGetSymbolAddress(&h1p, g_h1);
    float* h1 = (float*)h1p;

    int tgrid = (N + 31) / 32;
    int ggrid = (N + 7) / 8;
    int egrid = (E + 255) / 256;
    int ngrid = (N + 255) / 256;

    // K1: transform layer-1 ∥ zero+detect
    prep_kernel<<<tgrid + ngrid, 256>>>(h, W0, b0, N, tgrid,
                                        (const long long*)edges, E, N);
    // K2: single-pass padded-CSR fill
    fill_kernel<<<egrid, 256>>>(edges, edge_mask, E);
    // K3: layer-1 aggregate+activate
    gather_finalize_kernel<<<ggrid, 256>>>(node_mask, h1, N);
    // K4..K5: layer 2
    transform_kernel<<<tgrid, 256>>>(h1, W1, b1, N);
    gather_finalize_kernel<<<ggrid, 256>>>(node_mask, out, N);
}

// round 17
// speedup vs baseline: 1.5793x; 1.1687x over previous
#include <cuda_runtime.h>
#include <cuda_fp16.h>
#include <cuda_bf16.h>
#include <stdint.h>

#define NMAX 50000
#define DIM  64
#define CAP  96     // padded-CSR capacity per node (mean deg ~24; P(>96) ~ e^-61)

// ---------------- scratch (static device globals; no allocation) -------------
__device__ __align__(128) __half g_ht16[(size_t)NMAX * DIM]; // tangent feats (fp16, interleaved)
__device__ __align__(128) float  g_h1[(size_t)NMAX * DIM];   // layer-1 output
__device__ int   g_cnt[NMAX];                 // per-node fill cursor == degree count
__device__ int2  g_cm[(size_t)NMAX * CAP];    // padded CSR: (col, mask-bits)
__device__ int   g_is64;

// ---------------- helpers ----------------------------------------------------
__device__ __forceinline__ float wsum(float v) {
#pragma unroll
    for (int o = 16; o; o >>= 1) v += __shfl_xor_sync(0xffffffffu, v, o);
    return v;
}
__device__ __forceinline__ float artanh_c(float x) {
    x = fminf(fmaxf(x, -1.0f + 1e-5f), 1.0f - 1e-5f);
    return 0.5f * __logf(__fdividef(1.0f + x, 1.0f - x));
}
__device__ __forceinline__ float tanh_c(float x) {
    x = fminf(fmaxf(x, -15.0f), 15.0f);
    float e = __expf(2.0f * x);
    return __fdividef(e - 1.0f, e + 1.0f);
}
__device__ __forceinline__ void mma_16x8x16(float c[4], uint32_t a0, uint32_t a1,
                                            uint32_t a2, uint32_t a3,
                                            uint32_t b0, uint32_t b1) {
    asm volatile(
        "mma.sync.aligned.m16n8k16.row.col.f32.f16.f16.f32 "
        "{%0,%1,%2,%3}, {%4,%5,%6,%7}, {%8,%9}, {%0,%1,%2,%3};"
        : "+f"(c[0]), "+f"(c[1]), "+f"(c[2]), "+f"(c[3])
        : "r"(a0), "r"(a1), "r"(a2), "r"(a3), "r"(b0), "r"(b1));
}

// ---------------- transform body: HMMA GEMM + HypLinear epilogue --------------
// Block = 256 threads, 32 nodes. GEMM: mx[32x64] = x[32x64] * W^T via
// mma.m16n8k16 (fp16 in, fp32 acc). Epilogue identical to R16 (fp32).
#define PADA 72   // halves per sA row (conflict-free: 36g+tg distinct banks)
#define PADB 72
#define PADC 65   // floats per smx row

__device__ __forceinline__ void transform_body(const float* __restrict__ x,
                                               const float* __restrict__ W,
                                               const float* __restrict__ b,
                                               int n, int bid)
{
    __shared__ __align__(16) __half sA[32 * PADA];
    __shared__ __align__(16) __half sB[64 * PADB];
    __shared__ float smx[32 * PADC];
    __shared__ float sbias[64];
    __shared__ float sy2;

    const int tid = threadIdx.x, warp = tid >> 5, lane = tid & 31;
    const int nodebase = bid * 32;

    // ---- stage W -> sB (fp16), 8 halves per chunk, 512 chunks ----
    for (int cidx = tid; cidx < 512; cidx += 256) {
        int r = cidx >> 3, cc = cidx & 7;
        float4 w0 = *(const float4*)&W[r * 64 + cc * 8];
        float4 w1 = *(const float4*)&W[r * 64 + cc * 8 + 4];
        __half2 h0 = __floats2half2_rn(w0.x, w0.y);
        __half2 h1 = __floats2half2_rn(w0.z, w0.w);
        __half2 h2 = __floats2half2_rn(w1.x, w1.y);
        __half2 h3 = __floats2half2_rn(w1.z, w1.w);
        uint4 u;
        u.x = *(uint32_t*)&h0; u.y = *(uint32_t*)&h1;
        u.z = *(uint32_t*)&h2; u.w = *(uint32_t*)&h3;
        *(uint4*)&sB[r * PADB + cc * 8] = u;
    }
    // ---- stage x -> sA (fp16), 256 chunks ----
    {
        int r = tid >> 3, cc = tid & 7;
        int node = nodebase + r;
        float4 v0 = make_float4(0.f, 0.f, 0.f, 0.f);
        float4 v1 = v0;
        if (node < n) {
            v0 = *(const float4*)&x[(size_t)node * 64 + cc * 8];
            v1 = *(const float4*)&x[(size_t)node * 64 + cc * 8 + 4];
        }
        __half2 h0 = __floats2half2_rn(v0.x, v0.y);
        __half2 h1 = __floats2half2_rn(v0.z, v0.w);
        __half2 h2 = __floats2half2_rn(v1.x, v1.y);
        __half2 h3 = __floats2half2_rn(v1.z, v1.w);
        uint4 u;
        u.x = *(uint32_t*)&h0; u.y = *(uint32_t*)&h1;
        u.z = *(uint32_t*)&h2; u.w = *(uint32_t*)&h3;
        *(uint4*)&sA[r * PADA + cc * 8] = u;
    }
    // ---- hyperbolic bias (warp 0) ----
    if (warp == 0) {
        float b0 = b[lane], b1 = b[lane + 32];
        float bn = fmaxf(sqrtf(wsum(b0 * b0 + b1 * b1)), 1e-7f);
        float t  = tanh_c(bn);
        float inv = __fdividef(t, bn);
        float p0 = inv * b0, p1 = inv * b1;
        float pn2 = wsum(p0 * p0 + p1 * p1);
        float pn  = fmaxf(sqrtf(pn2), 1e-7f);
        if (pn > 1.0f - 1e-5f) { float s = (1.0f - 1e-5f) / pn; p0 *= s; p1 *= s; pn2 *= s * s; }
        sbias[lane] = p0; sbias[lane + 32] = p1;
        if (lane == 0) sy2 = pn2;
    }
    __syncthreads();

    // ---- MMA phase: warp -> (mtile = warp>>2, ntiles 2*(warp&3), +1) ----
    {
        int g  = lane >> 2;        // 0..7
        int tg = lane & 3;         // 0..3
        int mt = warp >> 2;        // 0..1
        int nt0 = (warp & 3) * 2;  // 0,2,4,6
        float c0[4] = {0.f, 0.f, 0.f, 0.f};
        float c1[4] = {0.f, 0.f, 0.f, 0.f};
        int arow0 = (mt * 16 + g) * PADA;
        int arow1 = arow0 + 8 * PADA;
        int brow0 = (nt0 * 8 + g) * PADB;
        int brow1 = brow0 + 8 * PADB;
#pragma unroll
        for (int ks = 0; ks < 4; ks++) {
            int kc = ks * 16 + tg * 2;
            uint32_t a0 = *(uint32_t*)&sA[arow0 + kc];
            uint32_t a1 = *(uint32_t*)&sA[arow1 + kc];
            uint32_t a2 = *(uint32_t*)&sA[arow0 + kc + 8];
            uint32_t a3 = *(uint32_t*)&sA[arow1 + kc + 8];
            uint32_t b0 = *(uint32_t*)&sB[brow0 + kc];
            uint32_t b1 = *(uint32_t*)&sB[brow0 + kc + 8];
            uint32_t b2 = *(uint32_t*)&sB[brow1 + kc];
            uint32_t b3 = *(uint32_t*)&sB[brow1 + kc + 8];
            mma_16x8x16(c0, a0, a1, a2, a3, b0, b1);
            mma_16x8x16(c1, a0, a1, a2, a3, b2, b3);
        }
        int row = mt * 16 + g;
        int col0 = nt0 * 8 + tg * 2;
        smx[row * PADC + col0]            = c0[0];
        smx[row * PADC + col0 + 1]        = c0[1];
        smx[(row + 8) * PADC + col0]      = c0[2];
        smx[(row + 8) * PADC + col0 + 1]  = c0[3];
        smx[row * PADC + col0 + 8]        = c1[0];
        smx[row * PADC + col0 + 9]        = c1[1];
        smx[(row + 8) * PADC + col0 + 8]  = c1[2];
        smx[(row + 8) * PADC + col0 + 9]  = c1[3];
    }
    __syncthreads();

    // ---- epilogue: warp per 4 nodes (R16-proven math) ----
    float y2 = sy2;
    float p0 = sbias[lane], p1 = sbias[lane + 32];
    __half2* ht2 = (__half2*)g_ht16;
    int rbase = warp * 4;

#pragma unroll
    for (int r = 0; r < 4; r++) {
        int node = nodebase + rbase + r;
        if (node >= n) break;
        float a0 = smx[(rbase + r) * PADC + lane];
        float a1 = smx[(rbase + r) * PADC + lane + 32];
        float xv0 = x[(size_t)node * 64 + lane];
        float xv1 = x[(size_t)node * 64 + 32 + lane];
        float xn  = fmaxf(sqrtf(wsum(xv0 * xv0 + xv1 * xv1)), 1e-7f);
        float mxn = fmaxf(sqrtf(wsum(a0 * a0 + a1 * a1)), 1e-7f);
        float t   = tanh_c(__fdividef(mxn, xn) * artanh_c(xn));
        float hn = fminf(t, 1.0f - 1e-5f);
        float inv1 = __fdividef(hn, mxn);
        float h0 = inv1 * a0, h1 = inv1 * a1;
        float hn2 = hn * hn;
        float xy  = wsum(h0 * p0 + h1 * p1);
        float cA  = 1.0f + 2.0f * xy + y2;
        float cB  = 1.0f - hn2;
        float den = fmaxf(1.0f + 2.0f * xy + hn2 * y2, 1e-7f);
        float invden = __fdividef(1.0f, den);
        float q0 = (cA * h0 + cB * p0) * invden;
        float q1 = (cA * h1 + cB * p1) * invden;
        float qn = fmaxf(sqrtf(wsum(q0 * q0 + q1 * q1)), 1e-7f);
        if (qn > 1.0f - 1e-5f) { float s = __fdividef(1.0f - 1e-5f, qn); q0 *= s; q1 *= s; qn = 1.0f - 1e-5f; }
        float l = __fdividef(artanh_c(qn), qn);
        ht2[(size_t)node * 32 + lane] = __floats2half2_rn(l * q0, l * q1);
    }
}

// ---------------- K1: transform layer-1  ∥  zero counters + dtype detect -----
__global__ void prep_kernel(const float* __restrict__ x,
                            const float* __restrict__ W,
                            const float* __restrict__ b,
                            int n, int tgrid,
                            const long long* __restrict__ e64, int E, int N)
{
    if ((int)blockIdx.x < tgrid) {
        transform_body(x, W, b, n, blockIdx.x);
        return;
    }
    int i = ((int)blockIdx.x - tgrid) * 256 + threadIdx.x;
    if (i < n) g_cnt[i] = 0;
    if (i == 0) {
        int ok = 1;
        int cnt = E < 64 ? E : 64;
        for (int k = 0; k < cnt; k++) {
            long long v = e64[k];
            if (v < 0 || v >= (long long)N) { ok = 0; break; }
        }
        g_is64 = ok;
    }
}

// plain transform launch (layer 2)
__global__ void transform_kernel(const float* __restrict__ x,
                                 const float* __restrict__ W,
                                 const float* __restrict__ b,
                                 int n)
{
    transform_body(x, W, b, n, blockIdx.x);
}

// ---------------- K2: single-pass padded-CSR fill ------------------------------
__global__ void fill_kernel(const void* __restrict__ edges_raw,
                            const float* __restrict__ em, int E)
{
    int eid = blockIdx.x * blockDim.x + threadIdx.x;
    if (eid >= E) return;
    int r, c;
    if (g_is64) {
        const long long* e = (const long long*)edges_raw;
        r = (int)__ldg(&e[eid]);
        c = (int)__ldg(&e[(size_t)E + eid]);
    } else {
        const int* e = (const int*)edges_raw;
        r = __ldg(&e[eid]);
        c = __ldg(&e[(size_t)E + eid]);
    }
    float m = __ldg(&em[eid]);
    int rank = atomicAdd(&g_cnt[r], 1);
    if (rank < CAP)
        g_cm[(size_t)r * CAP + rank] = make_int2(c, __float_as_int(m));
}

// ---------------- gather + HypAgg + HypAct (R16-proven) ------------------------
__global__ void __launch_bounds__(256)
gather_finalize_kernel(const float* __restrict__ node_mask,
                       float* __restrict__ out, int n)
{
    int warp = threadIdx.x >> 5, lane = threadIdx.x & 31;
    int node = blockIdx.x * 8 + warp;
    if (node >= n) return;

    int cntv = g_cnt[node]; if (cntv > CAP) cntv = CAP;
    int beg = node * CAP, end = beg + cntv;
    int quarter = lane >> 3, sub = lane & 7;

    const uint4* ht4 = (const uint4*)g_ht16;   // row = 8 x uint4
    float2 facc[4];
#pragma unroll
    for (int w = 0; w < 4; w++) facc[w] = make_float2(0.f, 0.f);
    float dm = 0.f;

    for (int base = beg; base < end; base += 16) {
        int lim = end; if (lim > base + 16) lim = base + 16;
        __half2 hz = __float2half2_rn(0.f);
        __half2 hacc0 = hz, hacc1 = hz, hacc2 = hz, hacc3 = hz;
#pragma unroll 4
        for (int j = base + quarter; j < lim; j += 4) {
            int2 cm = __ldg(&g_cm[j]);
            float m = __int_as_float(cm.y);
            __half2 mh = __float2half2_rn(m);
            uint4 v = __ldg(&ht4[(size_t)cm.x * 8 + sub]);
            hacc0 = __hfma2(*(const __half2*)&v.x, mh, hacc0);
            hacc1 = __hfma2(*(const __half2*)&v.y, mh, hacc1);
            hacc2 = __hfma2(*(const __half2*)&v.z, mh, hacc2);
            hacc3 = __hfma2(*(const __half2*)&v.w, mh, hacc3);
            if (sub == 0) dm += m;
        }
        float2 f0 = __half22float2(hacc0);
        float2 f1 = __half22float2(hacc1);
        float2 f2 = __half22float2(hacc2);
        float2 f3 = __half22float2(hacc3);
        facc[0].x += f0.x; facc[0].y += f0.y;
        facc[1].x += f1.x; facc[1].y += f1.y;
        facc[2].x += f2.x; facc[2].y += f2.y;
        facc[3].x += f3.x; facc[3].y += f3.y;
    }

    float d = fmaxf(wsum(dm), 1.0f);

#pragma unroll
    for (int w = 0; w < 4; w++) {
        facc[w].x += __shfl_xor_sync(0xffffffffu, facc[w].x, 8);
        facc[w].y += __shfl_xor_sync(0xffffffffu, facc[w].y, 8);
        facc[w].x += __shfl_xor_sync(0xffffffffu, facc[w].x, 16);
        facc[w].y += __shfl_xor_sync(0xffffffffu, facc[w].y, 16);
    }

    float inv_d = __fdividef(1.0f, d);
    float a[8];
#pragma unroll
    for (int w = 0; w < 4; w++) { a[2*w] = facc[w].x * inv_d; a[2*w+1] = facc[w].y * inv_d; }

    float n2 = 0.f;
#pragma unroll
    for (int k = 0; k < 8; k++) n2 += a[k] * a[k];
    float an = fmaxf(sqrtf(wsum(n2) * 0.25f), 1e-7f);
    float t  = tanh_c(an);
    float hn = fminf(t, 1.0f - 1e-5f);
    float s1 = __fdividef(hn, an);
    float hh[8];
#pragma unroll
    for (int k = 0; k < 8; k++) hh[k] = s1 * a[k];

    float l = __fdividef(artanh_c(hn), hn);
    float u[8];
    float un2 = 0.f;
#pragma unroll
    for (int k = 0; k < 8; k++) { u[k] = fmaxf(l * hh[k], 0.f); un2 += u[k] * u[k]; }

    float un = fmaxf(sqrtf(wsum(un2) * 0.25f), 1e-7f);
    float t2 = tanh_c(un);
    float on = fminf(t2, 1.0f - 1e-5f);
    float s2 = __fdividef(on, un);
    float o[8];
#pragma unroll
    for (int k = 0; k < 8; k++) o[k] = s2 * u[k];

    if (quarter == 0) {
        float nm = node_mask[node];
        float4 lo = make_float4(o[0] * nm, o[2] * nm, o[4] * nm, o[6] * nm);
        float4 hi = make_float4(o[1] * nm, o[3] * nm, o[5] * nm, o[7] * nm);
        *(float4*)(out + (size_t)node * 64 + 4 * sub)      = lo;
        *(float4*)(out + (size_t)node * 64 + 32 + 4 * sub) = hi;
    }
}

// ---------------- launch -----------------------------------------------------
extern "C" void kernel_launch(void* const* d_in, const int* in_sizes, int n_in,
                              void* d_out, int out_size)
{
    const float* h         = (const float*)d_in[0];
    const void*  edges     = d_in[2];
    const float* node_mask = (const float*)d_in[3];
    const float* edge_mask = (const float*)d_in[4];
    const float* W0        = (const float*)d_in[5];
    const float* b0        = (const float*)d_in[6];
    const float* W1        = (const float*)d_in[7];
    const float* b1        = (const float*)d_in[8];
    float*       out       = (float*)d_out;

    int N = in_sizes[0] / 64;
    int E = in_sizes[4];

    void* h1p = nullptr;
    cudaGetSymbolAddress(&h1p, g_h1);
    float* h1 = (float*)h1p;

    int tgrid = (N + 31) / 32;
    int ggrid = (N + 7) / 8;
    int egrid = (E + 255) / 256;
    int ngrid = (N + 255) / 256;

    // K1: transform layer-1 ∥ zero+detect
    prep_kernel<<<tgrid + ngrid, 256>>>(h, W0, b0, N, tgrid,
                                        (const long long*)edges, E, N);
    // K2: single-pass padded-CSR fill
    fill_kernel<<<egrid, 256>>>(edges, edge_mask, E);
    // K3: layer-1 aggregate+activate
    gather_finalize_kernel<<<ggrid, 256>>>(node_mask, h1, N);
    // K4..K5: layer 2
    transform_kernel<<<tgrid, 256>>>(h1, W1, b1, N);
    gather_finalize_kernel<<<ggrid, 256>>>(node_mask, out, N);
}